// round 2
// baseline (speedup 1.0000x reference)
#include <cuda_runtime.h>

#define Nn     5000
#define PADN   5056          // 79 tiles * 64
#define LDX    36            // padded row stride for [N,33] feature buffers
#define NU     32
#define TENC   12
#define TDEC   12
#define BM     32
#define BK     64
#define SPLITK 8
#define NRT    157           // ceil(5000/32)
#define KTILES 79            // ceil(5000/64)
#define GGRID  (NRT*SPLITK)  // 1256

// ---------------- persistent device state (no allocations) ----------------
__device__ __align__(16) float g_X0[PADN*LDX];  // [x | h]
__device__ __align__(16) float g_X1[PADN*LDX];  // adj @ X0
__device__ __align__(16) float g_X2[PADN*LDX];  // adj @ X1
__device__ __align__(16) float g_C0[PADN*LDX];  // [x | r*h]
__device__ __align__(16) float g_C1[PADN*LDX];  // adj @ C0
__device__ __align__(16) float g_C2[PADN*LDX];  // adj @ C1
__device__ float g_h[Nn*NU];                    // hidden state
__device__ float g_u[Nn*NU];                    // update gate

// ---------------- async-copy helpers ----------------
__device__ __forceinline__ void cp_async4(void* dst, const void* src, int srcbytes) {
    unsigned s = (unsigned)__cvta_generic_to_shared(dst);
    asm volatile("cp.async.ca.shared.global [%0], [%1], 4, %2;\n"
                 :: "r"(s), "l"(src), "r"(srcbytes));
}
__device__ __forceinline__ void cp_async16(void* dst, const void* src) {
    unsigned s = (unsigned)__cvta_generic_to_shared(dst);
    asm volatile("cp.async.cg.shared.global [%0], [%1], 16;\n"
                 :: "r"(s), "l"(src));
}

// ============================================================================
// Big GEMM: Y += A(5000x5000) @ X(5000x33), X/Y row stride LDX=36.
// BM=32 rows/block, BK=64 k-tile, split-K=8, atomicAdd epilogue.
// Warp w (0..6) owns cols [4w,4w+4); warp 7 owns cols 28..31 plus col 32.
// Inner loop uses packed fp32x2 FMA (sm_103a FFMA2).
// ============================================================================
__global__ void __launch_bounds__(256) gemm33(const float* __restrict__ A, int sel)
{
    const float* __restrict__ X;
    float* __restrict__ Y;
    switch (sel) {
        case 0:  X = g_X0; Y = g_X1; break;
        case 1:  X = g_X1; Y = g_X2; break;
        case 2:  X = g_C0; Y = g_C1; break;
        default: X = g_C1; Y = g_C2; break;
    }

    __shared__ float As[2][BK][BM+1];                // [k][row], conflict-free
    __shared__ __align__(16) float Xs[2][BK][LDX];   // [k][col]

    const int t    = threadIdx.x;
    const int rt   = blockIdx.x % NRT;
    const int ck   = blockIdx.x / NRT;
    const int row0 = rt * BM;
    const int tS   = (KTILES * ck)       / SPLITK;
    const int tE   = (KTILES * (ck + 1)) / SPLITK;
    const int warp = t >> 5, lane = t & 31;
    const int c0   = warp * 4;

    // A-tile loader: 8 threads per row, 8 k-values each (4B cp.async into [k][row])
    const int lr = t >> 3;
    const int l8 = t & 7;
    int arow = row0 + lr; if (arow >= Nn) arow = Nn - 1;
    const float* aptr = A + (long)arow * Nn;

    auto loadTile = [&](int tile, int b) {
        const int k0 = tile * BK;
        #pragma unroll
        for (int j = 0; j < 8; ++j) {
            int k  = j * 8 + l8;
            int gk = k0 + k;
            int ok = (gk < Nn);
            cp_async4(&As[b][k][lr], aptr + (ok ? gk : 0), ok ? 4 : 0);
        }
        // X rows are contiguous (stride LDX): flat 16B copies; rows >= Nn are
        // zero-padded in the buffers so no guard is needed on k.
        const float* xsrc = X + (long)k0 * LDX;
        float* xdst = &Xs[b][0][0];
        #pragma unroll
        for (int j = 0; j < 3; ++j) {
            int c = j * 256 + t;
            if (c < (BK * LDX) / 4)
                cp_async16(xdst + c * 4, xsrc + c * 4);
        }
    };

    unsigned long long acc01 = 0ull, acc23 = 0ull;
    float acc32 = 0.f;

    loadTile(tS, 0);
    asm volatile("cp.async.commit_group;\n" ::: "memory");
    int buf = 0;
    for (int tt = tS; tt < tE; ++tt) {
        if (tt + 1 < tE) {
            loadTile(tt + 1, buf ^ 1);
            asm volatile("cp.async.commit_group;\n" ::: "memory");
            asm volatile("cp.async.wait_group 1;\n" ::: "memory");
        } else {
            asm volatile("cp.async.wait_group 0;\n" ::: "memory");
        }
        __syncthreads();

        if (warp < 7) {
            #pragma unroll 16
            for (int kk = 0; kk < BK; ++kk) {
                float a = As[buf][kk][lane];
                unsigned long long a2;
                asm("mov.b64 %0, {%1, %2};" : "=l"(a2) : "f"(a), "f"(a));
                ulonglong2 xv = *reinterpret_cast<const ulonglong2*>(&Xs[buf][kk][c0]);
                asm("fma.rn.f32x2 %0, %1, %2, %0;" : "+l"(acc01) : "l"(a2), "l"(xv.x));
                asm("fma.rn.f32x2 %0, %1, %2, %0;" : "+l"(acc23) : "l"(a2), "l"(xv.y));
            }
        } else {
            #pragma unroll 16
            for (int kk = 0; kk < BK; ++kk) {
                float a = As[buf][kk][lane];
                unsigned long long a2;
                asm("mov.b64 %0, {%1, %2};" : "=l"(a2) : "f"(a), "f"(a));
                ulonglong2 xv = *reinterpret_cast<const ulonglong2*>(&Xs[buf][kk][28]);
                asm("fma.rn.f32x2 %0, %1, %2, %0;" : "+l"(acc01) : "l"(a2), "l"(xv.x));
                asm("fma.rn.f32x2 %0, %1, %2, %0;" : "+l"(acc23) : "l"(a2), "l"(xv.y));
                acc32 = fmaf(a, Xs[buf][kk][32], acc32);
            }
        }
        __syncthreads();
        buf ^= 1;
    }

    const int row = row0 + lane;
    if (row < Nn) {
        float f0, f1, f2, f3;
        asm("mov.b64 {%0, %1}, %2;" : "=f"(f0), "=f"(f1) : "l"(acc01));
        asm("mov.b64 {%0, %1}, %2;" : "=f"(f2), "=f"(f3) : "l"(acc23));
        float* y = Y + (long)row * LDX + c0;
        atomicAdd(y + 0, f0);
        atomicAdd(y + 1, f1);
        atomicAdd(y + 2, f2);
        atomicAdd(y + 3, f3);
        if (warp == 7) atomicAdd(Y + (long)row * LDX + 32, acc32);
    }
}

// ============================================================================
// Small kernels
// ============================================================================
__global__ void init_k() {
    long i0 = (long)blockIdx.x * blockDim.x + threadIdx.x;
    long stride = (long)gridDim.x * blockDim.x;
    for (long i = i0; i < (long)PADN * LDX; i += stride) {
        g_X0[i] = 0.f; g_X1[i] = 0.f; g_X2[i] = 0.f;
        g_C0[i] = 0.f; g_C1[i] = 0.f; g_C2[i] = 0.f;
    }
    for (long i = i0; i < (long)Nn * NU; i += stride) g_h[i] = 0.f;
}

// X0 = [inputs[:,t] | h], zero X1, X2 (rows < Nn)
__global__ void build_enc(const float* __restrict__ inp, int tstep) {
    long i0 = (long)blockIdx.x * blockDim.x + threadIdx.x;
    long stride = (long)gridDim.x * blockDim.x;
    for (long i = i0; i < (long)Nn * 33; i += stride) {
        int n = (int)(i / 33), c = (int)(i % 33);
        g_X0[n * LDX + c] = (c == 0) ? inp[n * TENC + tstep] : g_h[n * NU + (c - 1)];
    }
    for (long i = i0; i < (long)Nn * LDX; i += stride) { g_X1[i] = 0.f; g_X2[i] = 0.f; }
}

// X0 = [0 | h], zero X1, X2  (first decoder step; GO symbol = 0)
__global__ void build_dec0() {
    long i0 = (long)blockIdx.x * blockDim.x + threadIdx.x;
    long stride = (long)gridDim.x * blockDim.x;
    for (long i = i0; i < (long)Nn * 33; i += stride) {
        int n = (int)(i / 33), c = (int)(i % 33);
        g_X0[n * LDX + c] = (c == 0) ? 0.f : g_h[n * NU + (c - 1)];
    }
    for (long i = i0; i < (long)Nn * LDX; i += stride) { g_X1[i] = 0.f; g_X2[i] = 0.f; }
}

// ru = sigmoid([X0|X1|X2] @ Wg + bg); C0 = [x | r*h]; g_u = u; zero C1, C2.
// 4 rows/block, 64 cols. Wg: [99, 64] row-major.
__global__ void __launch_bounds__(256) gate_k(const float* __restrict__ W,
                                              const float* __restrict__ b) {
    __shared__ float sW[99 * 64];
    __shared__ float sb[64];
    int t = threadIdx.x;
    for (int i = t; i < 99 * 64; i += 256) sW[i] = W[i];
    if (t < 64) sb[t] = b[t];
    __syncthreads();

    int row = blockIdx.x * 4 + (t >> 6);
    int col = t & 63;
    if (row < Nn) {
        const float* x0 = g_X0 + row * LDX;
        const float* x1 = g_X1 + row * LDX;
        const float* x2 = g_X2 + row * LDX;
        float acc = sb[col];
        #pragma unroll
        for (int k = 0; k < 33; ++k) acc = fmaf(x0[k], sW[k * 64 + col], acc);
        #pragma unroll
        for (int k = 0; k < 33; ++k) acc = fmaf(x1[k], sW[(33 + k) * 64 + col], acc);
        #pragma unroll
        for (int k = 0; k < 33; ++k) acc = fmaf(x2[k], sW[(66 + k) * 64 + col], acc);
        float s = 1.f / (1.f + expf(-acc));
        if (col < NU) {
            g_C0[row * LDX + 1 + col] = s * g_h[row * NU + col];   // r * h
            if (col == 0) g_C0[row * LDX] = x0[0];                 // x
        } else {
            g_u[row * NU + (col - NU)] = s;                        // u
        }
    }
    long i0 = (long)blockIdx.x * blockDim.x + t;
    long stride = (long)gridDim.x * blockDim.x;
    for (long i = i0; i < (long)Nn * LDX; i += stride) { g_C1[i] = 0.f; g_C2[i] = 0.f; }
}

// c = tanh([C0|C1|C2] @ Wc + bc); h = u*h + (1-u)*c.  Wc: [99, 32].
__global__ void __launch_bounds__(256) cand_k(const float* __restrict__ W,
                                              const float* __restrict__ b) {
    __shared__ float sW[99 * 32];
    __shared__ float sb[32];
    int t = threadIdx.x;
    for (int i = t; i < 99 * 32; i += 256) sW[i] = W[i];
    if (t < 32) sb[t] = b[t];
    __syncthreads();

    int row = blockIdx.x * 8 + (t >> 5);
    int col = t & 31;
    if (row >= Nn) return;
    const float* c0 = g_C0 + row * LDX;
    const float* c1 = g_C1 + row * LDX;
    const float* c2 = g_C2 + row * LDX;
    float acc = sb[col];
    #pragma unroll
    for (int k = 0; k < 33; ++k) acc = fmaf(c0[k], sW[k * 32 + col], acc);
    #pragma unroll
    for (int k = 0; k < 33; ++k) acc = fmaf(c1[k], sW[(33 + k) * 32 + col], acc);
    #pragma unroll
    for (int k = 0; k < 33; ++k) acc = fmaf(c2[k], sW[(66 + k) * 32 + col], acc);
    float c = tanhf(acc);
    float u = g_u[row * NU + col];
    float h = g_h[row * NU + col];
    g_h[row * NU + col] = u * h + (1.f - u) * c;
}

// out[:, t] = h @ Wp + bp; X0 = [out | h]; zero X1, X2.  One warp per row.
__global__ void __launch_bounds__(256) dec_post(const float* __restrict__ Wp,
                                                const float* __restrict__ bp,
                                                float* __restrict__ out, int tstep) {
    int t = threadIdx.x, lane = t & 31, warp = t >> 5;
    int row = blockIdx.x * 8 + warp;
    if (row < Nn) {
        float hv = g_h[row * NU + lane];
        float p = hv * Wp[lane];
        #pragma unroll
        for (int o = 16; o > 0; o >>= 1) p += __shfl_xor_sync(0xFFFFFFFFu, p, o);
        p += bp[0];
        if (lane == 0) {
            out[row * TDEC + tstep] = p;
            g_X0[row * LDX] = p;
        }
        g_X0[row * LDX + 1 + lane] = hv;
    }
    long i0 = (long)blockIdx.x * blockDim.x + t;
    long stride = (long)gridDim.x * blockDim.x;
    for (long i = i0; i < (long)Nn * LDX; i += stride) { g_X1[i] = 0.f; g_X2[i] = 0.f; }
}

// ============================================================================
// Host launch sequence (graph-capturable: kernel launches only)
// ============================================================================
extern "C" void kernel_launch(void* const* d_in, const int* in_sizes, int n_in,
                              void* d_out, int out_size) {
    const float* inputs = (const float*)d_in[0];
    // d_in[1] = targets (unused in eval mode)
    const float* adj    = (const float*)d_in[2];
    const float* enc_Wg = (const float*)d_in[3];
    const float* enc_bg = (const float*)d_in[4];
    const float* enc_Wc = (const float*)d_in[5];
    const float* enc_bc = (const float*)d_in[6];
    const float* dec_Wg = (const float*)d_in[7];
    const float* dec_bg = (const float*)d_in[8];
    const float* dec_Wc = (const float*)d_in[9];
    const float* dec_bc = (const float*)d_in[10];
    const float* dec_Wp = (const float*)d_in[11];
    const float* dec_bp = (const float*)d_in[12];
    float* out = (float*)d_out;

    init_k<<<1024, 256>>>();

    // ---- encoder ----
    for (int t = 0; t < TENC; ++t) {
        build_enc<<<645, 256>>>(inputs, t);
        gemm33<<<GGRID, 256>>>(adj, 0);   // X1 = A @ X0
        gemm33<<<GGRID, 256>>>(adj, 1);   // X2 = A @ X1
        gate_k<<<1250, 256>>>(enc_Wg, enc_bg);
        gemm33<<<GGRID, 256>>>(adj, 2);   // C1 = A @ C0
        gemm33<<<GGRID, 256>>>(adj, 3);   // C2 = A @ C1
        cand_k<<<625, 256>>>(enc_Wc, enc_bc);
    }

    // ---- decoder (autoregressive) ----
    build_dec0<<<645, 256>>>();
    for (int t = 0; t < TDEC; ++t) {
        gemm33<<<GGRID, 256>>>(adj, 0);
        gemm33<<<GGRID, 256>>>(adj, 1);
        gate_k<<<1250, 256>>>(dec_Wg, dec_bg);
        gemm33<<<GGRID, 256>>>(adj, 2);
        gemm33<<<GGRID, 256>>>(adj, 3);
        cand_k<<<625, 256>>>(dec_Wc, dec_bc);
        dec_post<<<625, 256>>>(dec_Wp, dec_bp, out, t);
    }
}

// round 3
// speedup vs baseline: 1.3724x; 1.3724x over previous
#include <cuda_runtime.h>

#define Nn     5000
#define TST    5024          // transposed buffer node stride (157*32)
#define NF     33
#define NU     32
#define TENC   12
#define TDEC   12
#define BM     256
#define BK     32
#define MT     20            // ceil(5000/256)
#define KT     157           // ceil(5000/32)
#define SPLITK 14
#define GGRID  (MT*SPLITK)   // 280

#define AS_W   (BM*36)       // 9216 words per A buffer
#define XS_W   (NF*36)       // 1188 words per X buffer
#define GEMM_SMEM ((2*AS_W + 2*XS_W)*4)   // 83232 bytes

// ------------- persistent device state (transposed: [feature][node]) -------------
__device__ float g_X0T[NF*TST];
__device__ float g_X1T[NF*TST];
__device__ float g_X2T[NF*TST];
__device__ float g_C0T[NF*TST];
__device__ float g_C1T[NF*TST];
__device__ float g_C2T[NF*TST];
__device__ float g_hT [NU*TST];
__device__ float g_uT [NU*TST];

// ------------- helpers -------------
__device__ __forceinline__ void cp16(void* dst, const void* src) {
    unsigned s = (unsigned)__cvta_generic_to_shared(dst);
    asm volatile("cp.async.cg.shared.global [%0], [%1], 16;\n" :: "r"(s), "l"(src));
}
__device__ __forceinline__ void cp16s(void* dst, const void* src, int bytes) {
    unsigned s = (unsigned)__cvta_generic_to_shared(dst);
    asm volatile("cp.async.cg.shared.global [%0], [%1], 16, %2;\n"
                 :: "r"(s), "l"(src), "r"(bytes));
}
__device__ __forceinline__ void ffma2(unsigned long long& acc,
                                      unsigned long long a, unsigned long long b) {
    asm("fma.rn.f32x2 %0, %1, %2, %0;" : "+l"(acc) : "l"(a), "l"(b));
}
__device__ __forceinline__ float sumb64(unsigned long long v) {
    float lo = __uint_as_float((unsigned)v);
    float hi = __uint_as_float((unsigned)(v >> 32));
    return lo + hi;
}

// ============================================================================
// Y^T += (A @ X)^T : A [5000x5000] row-major, X/Y transposed [33][TST].
// BM=256 rows, BK=32 k per tile, split-K=14, atomicAdd epilogue.
// Thread tile: 4 rows (lane + 32q + 128*half) x 8 cols (8*(warp&3)); warps with
// (warp&3)==0 also handle col 32. FFMA2 pairs along K.
// ============================================================================
__global__ void __launch_bounds__(256, 2) gemmT(const float* __restrict__ A, int sel)
{
    extern __shared__ float sm[];
    float* as = sm;               // [2][256][36]
    float* xs = sm + 2*AS_W;      // [2][33][36]

    const float* __restrict__ XT;
    float* __restrict__ YT;
    switch (sel) {
        case 0:  XT = g_X0T; YT = g_X1T; break;
        case 1:  XT = g_X1T; YT = g_X2T; break;
        case 2:  XT = g_C0T; YT = g_C1T; break;
        default: XT = g_C1T; YT = g_C2T; break;
    }

    const int t    = threadIdx.x;
    const int rt   = blockIdx.x % MT;
    const int ck   = blockIdx.x / MT;
    const int row0 = rt * BM;
    const int tS   = (KT * ck)       / SPLITK;
    const int tE   = (KT * (ck + 1)) / SPLITK;
    const int w    = t >> 5, lane = t & 31;
    const int half = w >> 2, cg = w & 3;
    const int rb   = half * 128;
    const int c0   = cg * 8;

    const int gr = row0 + t;
    const float* aRow = A + (long)(gr < Nn ? gr : Nn - 1) * Nn;
    const int xc = t >> 3, xch = t & 7;

    auto load_tile = [&](int tile, int b) {
        const int k0 = tile * BK;
        float* asb = as + b*AS_W + t*36;
        #pragma unroll
        for (int ch = 0; ch < 8; ++ch) {
            int kk = k0 + ch*4;
            int bytes = (gr < Nn && kk < Nn) ? 16 : 0;
            cp16s(asb + ch*4, aRow + (kk < Nn-3 ? kk : Nn-4), bytes);
        }
        float* xsb = xs + b*XS_W;
        cp16(xsb + xc*36 + xch*4, XT + xc*TST + k0 + xch*4);
        if (t < 8) cp16(xsb + 32*36 + t*4, XT + 32*TST + k0 + t*4);
    };

    unsigned long long acc[4][8];
    #pragma unroll
    for (int q = 0; q < 4; ++q)
        #pragma unroll
        for (int c = 0; c < 8; ++c) acc[q][c] = 0ull;
    unsigned long long a32[4] = {0ull, 0ull, 0ull, 0ull};

    load_tile(tS, 0);
    asm volatile("cp.async.commit_group;\n" ::: "memory");
    int buf = 0;
    for (int tt = tS; tt < tE; ++tt) {
        if (tt + 1 < tE) {
            load_tile(tt + 1, buf ^ 1);
            asm volatile("cp.async.commit_group;\n" ::: "memory");
            asm volatile("cp.async.wait_group 1;\n" ::: "memory");
        } else {
            asm volatile("cp.async.wait_group 0;\n" ::: "memory");
        }
        __syncthreads();

        const float* aB = as + buf*AS_W + (rb + lane)*36;
        const float* xB = xs + buf*XS_W;
        #pragma unroll
        for (int s = 0; s < 8; ++s) {
            ulonglong2 a2[4];
            #pragma unroll
            for (int q = 0; q < 4; ++q)
                a2[q] = *reinterpret_cast<const ulonglong2*>(aB + q*(32*36) + s*4);
            #pragma unroll
            for (int cp = 0; cp < 4; ++cp) {
                ulonglong2 x0 = *reinterpret_cast<const ulonglong2*>(xB + (c0 + 2*cp    )*36 + s*4);
                ulonglong2 x1 = *reinterpret_cast<const ulonglong2*>(xB + (c0 + 2*cp + 1)*36 + s*4);
                #pragma unroll
                for (int q = 0; q < 4; ++q) {
                    ffma2(acc[q][2*cp    ], a2[q].x, x0.x);
                    ffma2(acc[q][2*cp    ], a2[q].y, x0.y);
                    ffma2(acc[q][2*cp + 1], a2[q].x, x1.x);
                    ffma2(acc[q][2*cp + 1], a2[q].y, x1.y);
                }
            }
            if (cg == 0) {
                ulonglong2 xv = *reinterpret_cast<const ulonglong2*>(xB + 32*36 + s*4);
                #pragma unroll
                for (int q = 0; q < 4; ++q) {
                    ffma2(a32[q], a2[q].x, xv.x);
                    ffma2(a32[q], a2[q].y, xv.y);
                }
            }
        }
        __syncthreads();
        buf ^= 1;
    }

    #pragma unroll
    for (int q = 0; q < 4; ++q) {
        int r = row0 + rb + 32*q + lane;
        if (r < Nn) {
            #pragma unroll
            for (int c = 0; c < 8; ++c)
                atomicAdd(YT + (c0 + c)*TST + r, sumb64(acc[q][c]));
            if (cg == 0) atomicAdd(YT + 32*TST + r, sumb64(a32[q]));
        }
    }
}

// ============================================================================
// Small kernels (all transposed layout; lanes = consecutive nodes)
// ============================================================================
__global__ void init_k() {
    int tid = blockIdx.x * blockDim.x + threadIdx.x;
    int nth = gridDim.x * blockDim.x;
    for (int j = tid; j < NF*TST; j += nth) {
        g_X0T[j] = 0.f; g_X1T[j] = 0.f; g_X2T[j] = 0.f;
        g_C0T[j] = 0.f; g_C1T[j] = 0.f; g_C2T[j] = 0.f;
    }
    for (int j = tid; j < NU*TST; j += nth) { g_hT[j] = 0.f; g_uT[j] = 0.f; }
}

__global__ void build_enc(const float* __restrict__ inp, int tstep) {
    int tid = blockIdx.x * blockDim.x + threadIdx.x;
    int nth = gridDim.x * blockDim.x;
    for (int j = tid; j < NF*TST; j += nth) {
        int c = j / TST, n = j - c*TST;
        float v = 0.f;
        if (n < Nn) v = (c == 0) ? inp[n*TENC + tstep] : g_hT[(c-1)*TST + n];
        g_X0T[j] = v;
        g_X1T[j] = 0.f; g_X2T[j] = 0.f;
    }
}

__global__ void build_dec0() {
    int tid = blockIdx.x * blockDim.x + threadIdx.x;
    int nth = gridDim.x * blockDim.x;
    for (int j = tid; j < NF*TST; j += nth) {
        int c = j / TST, n = j - c*TST;
        float v = 0.f;
        if (n < Nn && c > 0) v = g_hT[(c-1)*TST + n];
        g_X0T[j] = v;
        g_X1T[j] = 0.f; g_X2T[j] = 0.f;
    }
}

// ru = sigmoid(W^T [x0|x1|x2] + b); r -> C0T = [x | r*h]; u -> g_uT; zero C1T,C2T.
__global__ void __launch_bounds__(256) gate_k(const float* __restrict__ W,
                                              const float* __restrict__ b) {
    __shared__ float sW[99*64];
    __shared__ float sx[99*32];
    const int t = threadIdx.x, lane = t & 31, w = t >> 5;
    const int rowb = blockIdx.x * 32;
    for (int j = t; j < 99*64; j += 256) sW[j] = W[j];
    for (int j = t; j < 99*32; j += 256) {
        int c = j >> 5, i = j & 31;
        const float* src = (c < 33) ? (g_X0T + c*TST)
                         : (c < 66) ? (g_X1T + (c-33)*TST)
                                    : (g_X2T + (c-66)*TST);
        sx[j] = src[rowb + i];
    }
    __syncthreads();

    float acc[8];
    #pragma unroll
    for (int cc = 0; cc < 8; ++cc) acc[cc] = b[8*w + cc];
    for (int k = 0; k < 99; ++k) {
        float xv = sx[k*32 + lane];
        const float4* wr = reinterpret_cast<const float4*>(sW + k*64 + 8*w);
        float4 w0 = wr[0], w1 = wr[1];
        acc[0] = fmaf(xv, w0.x, acc[0]); acc[1] = fmaf(xv, w0.y, acc[1]);
        acc[2] = fmaf(xv, w0.z, acc[2]); acc[3] = fmaf(xv, w0.w, acc[3]);
        acc[4] = fmaf(xv, w1.x, acc[4]); acc[5] = fmaf(xv, w1.y, acc[5]);
        acc[6] = fmaf(xv, w1.z, acc[6]); acc[7] = fmaf(xv, w1.w, acc[7]);
    }
    int row = rowb + lane;
    if (row < Nn) {
        #pragma unroll
        for (int cc = 0; cc < 8; ++cc) {
            int col = 8*w + cc;
            float s = 1.f / (1.f + expf(-acc[cc]));
            if (col < 32) g_C0T[(1 + col)*TST + row] = s * g_hT[col*TST + row];
            else          g_uT[(col - 32)*TST + row] = s;
        }
        if (w == 0) g_C0T[row] = g_X0T[row];
    }
    int tid = blockIdx.x * 256 + t, nth = gridDim.x * 256;
    for (int j = tid; j < NF*TST; j += nth) { g_C1T[j] = 0.f; g_C2T[j] = 0.f; }
}

// c = tanh(W^T [C0|C1|C2] + b); h = u*h + (1-u)*c.
__global__ void __launch_bounds__(256) cand_k(const float* __restrict__ W,
                                              const float* __restrict__ b) {
    __shared__ float sW[99*32];
    __shared__ float sx[99*32];
    const int t = threadIdx.x, lane = t & 31, w = t >> 5;
    const int rowb = blockIdx.x * 32;
    for (int j = t; j < 99*32; j += 256) sW[j] = W[j];
    for (int j = t; j < 99*32; j += 256) {
        int c = j >> 5, i = j & 31;
        const float* src = (c < 33) ? (g_C0T + c*TST)
                         : (c < 66) ? (g_C1T + (c-33)*TST)
                                    : (g_C2T + (c-66)*TST);
        sx[j] = src[rowb + i];
    }
    __syncthreads();

    float acc[4];
    #pragma unroll
    for (int cc = 0; cc < 4; ++cc) acc[cc] = b[4*w + cc];
    for (int k = 0; k < 99; ++k) {
        float xv = sx[k*32 + lane];
        float4 wv = *reinterpret_cast<const float4*>(sW + k*32 + 4*w);
        acc[0] = fmaf(xv, wv.x, acc[0]); acc[1] = fmaf(xv, wv.y, acc[1]);
        acc[2] = fmaf(xv, wv.z, acc[2]); acc[3] = fmaf(xv, wv.w, acc[3]);
    }
    int row = rowb + lane;
    if (row < Nn) {
        #pragma unroll
        for (int cc = 0; cc < 4; ++cc) {
            int col = 4*w + cc;
            float c = tanhf(acc[cc]);
            float u = g_uT[col*TST + row];
            float h = g_hT[col*TST + row];
            g_hT[col*TST + row] = u*h + (1.f - u)*c;
        }
    }
}

// out[:,t] = h @ Wp + bp; X0T = [out | h]; zero X1T, X2T.
__global__ void __launch_bounds__(256) dec_post(const float* __restrict__ Wp,
                                                const float* __restrict__ bp,
                                                float* __restrict__ out, int tstep) {
    int tid = blockIdx.x * 256 + threadIdx.x;
    int nth = gridDim.x * 256;
    for (int row = tid; row < Nn; row += nth) {
        float acc = bp[0];
        #pragma unroll
        for (int c = 0; c < 32; ++c) acc = fmaf(g_hT[c*TST + row], Wp[c], acc);
        out[row*TDEC + tstep] = acc;
        g_X0T[row] = acc;
    }
    for (int j = tid; j < NU*TST; j += nth) g_X0T[TST + j] = g_hT[j];
    for (int j = tid; j < NF*TST; j += nth) { g_X1T[j] = 0.f; g_X2T[j] = 0.f; }
}

// ============================================================================
// Host launch sequence (graph-capturable: kernel launches only)
// ============================================================================
extern "C" void kernel_launch(void* const* d_in, const int* in_sizes, int n_in,
                              void* d_out, int out_size) {
    const float* inputs = (const float*)d_in[0];
    const float* adj    = (const float*)d_in[2];
    const float* enc_Wg = (const float*)d_in[3];
    const float* enc_bg = (const float*)d_in[4];
    const float* enc_Wc = (const float*)d_in[5];
    const float* enc_bc = (const float*)d_in[6];
    const float* dec_Wg = (const float*)d_in[7];
    const float* dec_bg = (const float*)d_in[8];
    const float* dec_Wc = (const float*)d_in[9];
    const float* dec_bc = (const float*)d_in[10];
    const float* dec_Wp = (const float*)d_in[11];
    const float* dec_bp = (const float*)d_in[12];
    float* out = (float*)d_out;

    cudaFuncSetAttribute(gemmT, cudaFuncAttributeMaxDynamicSharedMemorySize, GEMM_SMEM);
    cudaFuncSetAttribute(gemmT, cudaFuncAttributePreferredSharedMemoryCarveout, 100);

    init_k<<<256, 256>>>();

    for (int t = 0; t < TENC; ++t) {
        build_enc<<<256, 256>>>(inputs, t);
        gemmT<<<GGRID, 256, GEMM_SMEM>>>(adj, 0);
        gemmT<<<GGRID, 256, GEMM_SMEM>>>(adj, 1);
        gate_k<<<157, 256>>>(enc_Wg, enc_bg);
        gemmT<<<GGRID, 256, GEMM_SMEM>>>(adj, 2);
        gemmT<<<GGRID, 256, GEMM_SMEM>>>(adj, 3);
        cand_k<<<157, 256>>>(enc_Wc, enc_bc);
    }

    build_dec0<<<256, 256>>>();
    for (int t = 0; t < TDEC; ++t) {
        gemmT<<<GGRID, 256, GEMM_SMEM>>>(adj, 0);
        gemmT<<<GGRID, 256, GEMM_SMEM>>>(adj, 1);
        gate_k<<<157, 256>>>(dec_Wg, dec_bg);
        gemmT<<<GGRID, 256, GEMM_SMEM>>>(adj, 2);
        gemmT<<<GGRID, 256, GEMM_SMEM>>>(adj, 3);
        cand_k<<<157, 256>>>(dec_Wc, dec_bc);
        dec_post<<<157, 256>>>(dec_Wp, dec_bp, out, t);
    }
}